// round 7
// baseline (speedup 1.0000x reference)
#include <cuda_runtime.h>
#include <math.h>
#include <stdint.h>

#define BB 4
#define NN 100000
#define KK 16
#define NPAIR (NN / 2)
#define EPSF 1e-6f
#define W_CE 2.0f
#define W_DICE 0.1f

#define GX 111                 // blocks per batch (444 total = 3/SM)
#define NBLK (GX * BB)
#define NWPB 8                 // warps per block
#define ENT 544                // padded slot; real: 256 D | 256 INTER | 16 S1M
#define NE_REAL 528
#define NE_TOT (BB * NE_REAL)  // 2112

struct Part { float e[ENT]; };
__device__ Part g_part[NBLK];
__device__ int g_count;        // self-resetting

// ---------------------------------------------------------------------------
__device__ __forceinline__ unsigned long long pack_dup(float x) {
    unsigned long long r;
    unsigned int u = __float_as_uint(x);
    asm("mov.b64 %0, {%1, %1};" : "=l"(r) : "r"(u));
    return r;
}
__device__ __forceinline__ void fma2(unsigned long long& acc,
                                     unsigned long long a,
                                     unsigned long long b) {
    asm("fma.rn.f32x2 %0, %1, %2, %0;" : "+l"(acc) : "l"(a), "l"(b));
}
__device__ __forceinline__ float lo32(unsigned long long x) {
    return __uint_as_float((unsigned int)(x & 0xffffffffULL));
}
__device__ __forceinline__ float hi32(unsigned long long x) {
    return __uint_as_float((unsigned int)(x >> 32));
}

// one iteration's register payload
struct __align__(16) Ld {
    float m;
    float2 v;
    ulonglong2 o0, o1, x0, x1;
};

// ---------------------------------------------------------------------------
__global__ void __launch_bounds__(256, 3) fused_kernel(
    const float* __restrict__ mask,
    const float* __restrict__ gt,
    const float* __restrict__ valid,
    float* __restrict__ out) {
    __shared__ float pti[NWPB][ENT];
    __shared__ float v1m[NWPB][32];
    __shared__ float facc[NE_TOT];
    __shared__ float cost[BB][KK][KK];
    __shared__ float mS1M[BB][KK], mSUMM[BB][KK], mSUMG[BB][KK], mV[BB];
    __shared__ int colmap[BB][KK];
    __shared__ float rce[BB * KK], rdice[BB * KK];
    __shared__ int is_last;

    const int b = blockIdx.y;
    const int bx = blockIdx.x;
    const int t = threadIdx.x;
    const int lane = t & 31;
    const int w = t >> 5;
    const int i = lane & 15;   // cost-row index owned by this lane
    const int jh = lane >> 4;  // j-half owned; also row-of-pair
    const unsigned FULL = 0xffffffffu;
    const int gwarp = bx * NWPB + w;
    const int nw = GX * NWPB;  // 888 warps per batch

    const float* mask_b = mask + (size_t)b * NN * KK;
    const float* gt_b = gt + (size_t)b * NN * KK;
    const float* val_b = valid + (size_t)b * NN;

    // precomputed lane-relative gt offsets (floats)
    const int oo0 = jh * 24;
    const int oo1 = jh * 24 + 4;
    const int ox0 = 16 - 8 * jh;
    const int ox1 = 20 - 8 * jh;
    const int om = lane;

    unsigned long long aD[4], aI[4];
#pragma unroll
    for (int k = 0; k < 4; k++) { aD[k] = 0ull; aI[k] = 0ull; }
    float s1m = 0.0f;   // accumulates +v*log2(1-m); negated at writeback

    Ld A, B;

#define DO_LOAD(L, pr)                                                        \
    do {                                                                      \
        const float* gbase = gt_b + (size_t)(pr) * 32;                        \
        (L).m = mask_b[(size_t)(pr) * 32 + om];                               \
        (L).v = *(const float2*)(val_b + (size_t)(pr) * 2);                   \
        (L).o0 = *(const ulonglong2*)(gbase + oo0);                           \
        (L).o1 = *(const ulonglong2*)(gbase + oo1);                           \
        (L).x0 = *(const ulonglong2*)(gbase + ox0);                           \
        (L).x1 = *(const ulonglong2*)(gbase + ox1);                           \
    } while (0)

#define DO_COMPUTE(L)                                                         \
    do {                                                                      \
        float vown = jh ? (L).v.y : (L).v.x;                                  \
        float l1 = __log2f((L).m);                                            \
        float l2 = __log2f(1.0f - (L).m);                                     \
        float down = vown * (l2 - l1);                                        \
        float rown = vown * (L).m;                                            \
        s1m = fmaf(vown, l2, s1m);                                            \
        float doth = __shfl_xor_sync(FULL, down, 16);                         \
        float roth = __shfl_xor_sync(FULL, rown, 16);                         \
        unsigned long long Dw = pack_dup(down), Rw = pack_dup(rown);          \
        unsigned long long Dx = pack_dup(doth), Rx = pack_dup(roth);          \
        fma2(aD[0], Dw, (L).o0.x); fma2(aD[1], Dw, (L).o0.y);                 \
        fma2(aD[2], Dw, (L).o1.x); fma2(aD[3], Dw, (L).o1.y);                 \
        fma2(aI[0], Rw, (L).o0.x); fma2(aI[1], Rw, (L).o0.y);                 \
        fma2(aI[2], Rw, (L).o1.x); fma2(aI[3], Rw, (L).o1.y);                 \
        fma2(aD[0], Dx, (L).x0.x); fma2(aD[1], Dx, (L).x0.y);                 \
        fma2(aD[2], Dx, (L).x1.x); fma2(aD[3], Dx, (L).x1.y);                 \
        fma2(aI[0], Rx, (L).x0.x); fma2(aI[1], Rx, (L).x0.y);                 \
        fma2(aI[2], Rx, (L).x1.x); fma2(aI[3], Rx, (L).x1.y);                 \
    } while (0)

    // ---- manual depth-2 pipelined main loop ----
    {
        int pr = gwarp;                 // < NPAIR always (888 < 50000)
        DO_LOAD(A, pr);
        while (true) {
            int prB = pr + nw;
            if (prB < NPAIR) {
                DO_LOAD(B, prB);
                DO_COMPUTE(A);
            } else {
                DO_COMPUTE(A);
                break;
            }
            int prA = prB + nw;
            if (prA < NPAIR) {
                DO_LOAD(A, prA);
                DO_COMPUTE(B);
            } else {
                DO_COMPUTE(B);
                break;
            }
            pr = prA;
        }
    }

    // ---- per-warp -> shared ----
    v1m[w][lane] = s1m;
    {
        const int basej = i * 16 + jh * 8;
#pragma unroll
        for (int k = 0; k < 4; k++) {
            pti[w][basej + 2 * k] = lo32(aD[k]);
            pti[w][basej + 2 * k + 1] = hi32(aD[k]);
            pti[w][256 + basej + 2 * k] = lo32(aI[k]);
            pti[w][256 + basej + 2 * k + 1] = hi32(aI[k]);
        }
    }
    __syncthreads();

    // ---- block reduce -> deterministic per-block partial slot ----
    Part* gp = &g_part[b * GX + bx];
#pragma unroll
    for (int e0 = 0; e0 < 512; e0 += 256) {
        int e = e0 + t;
        float sum = 0.0f;
#pragma unroll
        for (int ww = 0; ww < NWPB; ww++) sum += pti[ww][e];
        gp->e[e] = sum;
    }
    if (t < 16) {
        float sum = 0.0f;
#pragma unroll
        for (int ww = 0; ww < NWPB; ww++) sum += v1m[ww][t] + v1m[ww][t + 16];
        gp->e[512 + t] = -sum;   // S1M = -sum(v*log2(1-m))
    }

    __threadfence();
    __syncthreads();
    if (t == 0) {
        int old = atomicAdd(&g_count, 1);
        is_last = (old == NBLK - 1);
    }
    __syncthreads();
    if (!is_last) return;

    if (t == 0) g_count = 0;

    // ---- final reduce: 9 entries per thread, jammed for MLP ----
    {
        float sacc[9];
        const float* bas[9];
        int ok[9];
#pragma unroll
        for (int k = 0; k < 9; k++) {
            int q = t + k * 256;
            ok[k] = (q < NE_TOT);
            sacc[k] = 0.0f;
            if (ok[k]) {
                int bb2 = q / NE_REAL;
                int e = q - bb2 * NE_REAL;
                bas[k] = &g_part[bb2 * GX].e[e];
            } else {
                bas[k] = &g_part[0].e[0];
            }
        }
        for (int gx = 0; gx < GX; gx++) {
#pragma unroll
            for (int k = 0; k < 9; k++)
                if (ok[k]) sacc[k] += bas[k][(size_t)gx * ENT];
        }
#pragma unroll
        for (int k = 0; k < 9; k++) {
            int q = t + k * 256;
            if (ok[k]) facc[q] = sacc[k];
        }
    }
    __syncthreads();

    // ---- marginals from INTER (+ direct S1M) ----
    if (t < BB * KK) {
        int bb2 = t / KK, q = t % KK;
        const float* F = facc + bb2 * NE_REAL;
        float summ = 0.0f, sumg = 0.0f;
#pragma unroll
        for (int x = 0; x < KK; x++) {
            summ += F[256 + q * 16 + x];   // row sum of INTER
            sumg += F[256 + x * 16 + q];   // col sum of INTER
        }
        mS1M[bb2][q] = F[512 + q];
        mSUMM[bb2][q] = summ;
        mSUMG[bb2][q] = sumg;
    }
    __syncthreads();
    if (t < BB) {
        float v = 0.0f;
#pragma unroll
        for (int x = 0; x < KK; x++) v += mSUMG[t][x];
        mV[t] = v;
    }
    __syncthreads();

    // ---- cost matrices ----
    const float LN2 = 0.69314718055994530942f;
    for (int idx = t; idx < BB * 256; idx += 256) {
        int bb2 = idx >> 8;
        int r = idx & 255;
        int ii = r >> 4, jj = r & 15;
        const float* F = facc + bb2 * NE_REAL;
        float denom = fmaxf(mV[bb2], 1.0f);
        float ce = LN2 * (F[ii * 16 + jj] + mS1M[bb2][ii]) / denom;
        float dice = 1.0f - 2.0f * F[256 + ii * 16 + jj] /
                                (mSUMM[bb2][ii] + mSUMG[bb2][jj] + EPSF);
        cost[bb2][ii][jj] = W_CE * ce + W_DICE * dice;
    }
    __syncthreads();

    // ---- warp-parallel Hungarian (JV), one warp per batch ----
    if (w < BB) {
        const int bb2 = w;
        float ur = 0.0f;
        float vv = 0.0f;
        int pcol = 0;

        for (int ii = 1; ii <= KK; ii++) {
            if (lane == 0) pcol = ii;
            float minv = 1e30f;
            int way = 0;
            int used = 0;
            int rowcov = 0;
            int j0 = 0;

            while (true) {
                if (lane == j0) used = 1;
                int i0 = __shfl_sync(FULL, pcol, j0);
                if (lane == i0) rowcov = 1;
                float u_i0 = __shfl_sync(FULL, ur, i0);

                int active = (lane >= 1 && lane <= KK && !used);
                if (active) {
                    float c = cost[bb2][i0 - 1][lane - 1];
                    float cur = c - u_i0 - vv;
                    if (cur < minv) { minv = cur; way = j0; }
                }
                float val = active ? minv : 1e30f;
                float red = val;
#pragma unroll
                for (int off = 16; off; off >>= 1)
                    red = fminf(red, __shfl_xor_sync(FULL, red, off));
                unsigned bal = __ballot_sync(FULL, val == red);
                int j1 = __ffs(bal) - 1;
                float delta = red;

                if (rowcov) ur += delta;
                if (used) vv -= delta;
                else if (lane >= 1 && lane <= KK) minv -= delta;

                j0 = j1;
                int pj = __shfl_sync(FULL, pcol, j0);
                if (pj == 0) break;
            }
            while (j0 != 0) {
                int j1 = __shfl_sync(FULL, way, j0);
                int pv = __shfl_sync(FULL, pcol, j1);
                if (lane == j0) pcol = pv;
                j0 = j1;
            }
        }
        if (lane >= 1 && lane <= KK) colmap[bb2][pcol - 1] = lane - 1;
    }
    __syncthreads();

    // ---- loss ----
    if (t < BB * KK) {
        int bb2 = t / KK, ii = t % KK;
        int jj = colmap[bb2][ii];
        const float* F = facc + bb2 * NE_REAL;
        rce[t] = LN2 * (F[ii * 16 + jj] + mS1M[bb2][ii]);
        rdice[t] = 1.0f - 2.0f * F[256 + ii * 16 + jj] /
                              (mSUMM[bb2][ii] + mSUMG[bb2][jj] + EPSF);
    }
    __syncthreads();

    if (t == 0) {
        float cs = 0.0f, ds = 0.0f, vt = 0.0f;
        for (int x = 0; x < BB * KK; x++) { cs += rce[x]; ds += rdice[x]; }
        for (int bb2 = 0; bb2 < BB; bb2++) vt += mV[bb2];
        float l_ce = cs / (fmaxf(vt, 1.0f) * (float)KK);
        float l_dice = ds / (float)(BB * KK);
        out[0] = W_CE * l_ce + W_DICE * l_dice;
    }
}

// ---------------------------------------------------------------------------
extern "C" void kernel_launch(void* const* d_in, const int* in_sizes, int n_in,
                              void* d_out, int out_size) {
    const float* mask = (const float*)d_in[0];
    const float* gt = (const float*)d_in[1];
    const float* valid = (const float*)d_in[2];
    float* out = (float*)d_out;

    dim3 grid(GX, BB);
    fused_kernel<<<grid, 256>>>(mask, gt, valid, out);
}

// round 8
// speedup vs baseline: 1.2407x; 1.2407x over previous
#include <cuda_runtime.h>
#include <math.h>
#include <stdint.h>

#define BB 4
#define NN 100000
#define KK 16
#define NPAIR (NN / 2)
#define EPSF 1e-6f
#define W_CE 2.0f
#define W_DICE 0.1f

#define GX 74                  // blocks per batch (296 total = 2/SM)
#define NBLK (GX * BB)
#define NWPB 8                 // warps per block
#define NWARP (GX * NWPB)      // 592 warps per batch
#define UD 4                   // macro-iteration depth (pairs per group)
#define MITER ((NPAIR + UD * NWARP - 1) / (UD * NWARP))   // 22
#define ENT 544                // padded slot; real: 256 D | 256 INTER | 16 S1M
#define NE_REAL 528
#define NE_TOT (BB * NE_REAL)  // 2112

struct Part { float e[ENT]; };
__device__ Part g_part[NBLK];
__device__ int g_count;        // self-resetting

// ---------------------------------------------------------------------------
__device__ __forceinline__ unsigned long long pack_dup(float x) {
    unsigned long long r;
    unsigned int u = __float_as_uint(x);
    asm("mov.b64 %0, {%1, %1};" : "=l"(r) : "r"(u));
    return r;
}
__device__ __forceinline__ void fma2(unsigned long long& acc,
                                     unsigned long long a,
                                     unsigned long long b) {
    asm("fma.rn.f32x2 %0, %1, %2, %0;" : "+l"(acc) : "l"(a), "l"(b));
}
__device__ __forceinline__ float lo32(unsigned long long x) {
    return __uint_as_float((unsigned int)(x & 0xffffffffULL));
}
__device__ __forceinline__ float hi32(unsigned long long x) {
    return __uint_as_float((unsigned int)(x >> 32));
}

// ---------------------------------------------------------------------------
__global__ void __launch_bounds__(256, 2) fused_kernel(
    const float* __restrict__ mask,
    const float* __restrict__ gt,
    const float* __restrict__ valid,
    float* __restrict__ out) {
    __shared__ float pti[NWPB][ENT];
    __shared__ float v1m[NWPB][32];
    __shared__ float facc[NE_TOT];
    __shared__ float cost[BB][KK][KK];
    __shared__ float mS1M[BB][KK], mSUMM[BB][KK], mSUMG[BB][KK], mV[BB];
    __shared__ int colmap[BB][KK];
    __shared__ float rce[BB * KK], rdice[BB * KK];
    __shared__ int is_last;

    const int b = blockIdx.y;
    const int bx = blockIdx.x;
    const int t = threadIdx.x;
    const int lane = t & 31;
    const int w = t >> 5;
    const int i = lane & 15;   // cost-row index owned by this lane
    const int jh = lane >> 4;  // j-half owned; also row-of-pair
    const unsigned FULL = 0xffffffffu;
    const int gwarp = bx * NWPB + w;

    const float* mask_b = mask + (size_t)b * NN * KK;
    const float* gt_b = gt + (size_t)b * NN * KK;
    const float* val_b = valid + (size_t)b * NN;

    // lane-relative gt offsets (in floats); o/x chunks all within one 128B line
    const int oo0 = jh * 24;
    const int oo1 = jh * 24 + 4;
    const int ox0 = 16 - 8 * jh;
    const int ox1 = 20 - 8 * jh;
    const int om = lane;

    unsigned long long aD[4], aI[4];
#pragma unroll
    for (int k = 0; k < 4; k++) { aD[k] = 0ull; aI[k] = 0ull; }
    float s1m = 0.0f;   // accumulates +v*log2(1-m); negated at writeback

    // ---- main loop: UD-deep flat load phase, then compute phase ----
#pragma unroll 1
    for (int mi = 0; mi < MITER; mi++) {
        const int pr0 = gwarp + mi * (UD * NWARP);

        float mv[UD];
        float va[UD], vb[UD];
        unsigned long long go0x[UD], go0y[UD], go1x[UD], go1y[UD];
        unsigned long long gx0x[UD], gx0y[UD], gx1x[UD], gx1y[UD];

        // LOAD PHASE: 24 independent LDGs, front-batched
#pragma unroll
        for (int k = 0; k < UD; k++) {
            const int pr = pr0 + k * NWARP;
            const int ok = (pr < NPAIR);
            const size_t off = ok ? (size_t)pr * 32 : 0;
            const size_t voff = ok ? (size_t)pr * 2 : 0;
            const float* gb = gt_b + off;
            mv[k] = mask_b[off + om];
            float2 v2 = *(const float2*)(val_b + voff);
            va[k] = ok ? v2.x : 0.0f;
            vb[k] = ok ? v2.y : 0.0f;
            ulonglong2 u;
            u = *(const ulonglong2*)(gb + oo0); go0x[k] = u.x; go0y[k] = u.y;
            u = *(const ulonglong2*)(gb + oo1); go1x[k] = u.x; go1y[k] = u.y;
            u = *(const ulonglong2*)(gb + ox0); gx0x[k] = u.x; gx0y[k] = u.y;
            u = *(const ulonglong2*)(gb + ox1); gx1x[k] = u.x; gx1y[k] = u.y;
        }

        // COMPUTE PHASE
#pragma unroll
        for (int k = 0; k < UD; k++) {
            float vown = jh ? vb[k] : va[k];
            float mc = fminf(fmaxf(mv[k], EPSF), 1.0f - EPSF);
            float l1 = __log2f(mc);
            float l2 = __log2f(1.0f - mc);
            float down = vown * (l2 - l1);   // D weight (log2 space)
            float rown = vown * mv[k];       // INTER weight
            s1m = fmaf(vown, l2, s1m);

            float doth = __shfl_xor_sync(FULL, down, 16);
            float roth = __shfl_xor_sync(FULL, rown, 16);

            unsigned long long Dw = pack_dup(down), Rw = pack_dup(rown);
            unsigned long long Dx = pack_dup(doth), Rx = pack_dup(roth);

            fma2(aD[0], Dw, go0x[k]); fma2(aD[1], Dw, go0y[k]);
            fma2(aD[2], Dw, go1x[k]); fma2(aD[3], Dw, go1y[k]);
            fma2(aI[0], Rw, go0x[k]); fma2(aI[1], Rw, go0y[k]);
            fma2(aI[2], Rw, go1x[k]); fma2(aI[3], Rw, go1y[k]);

            fma2(aD[0], Dx, gx0x[k]); fma2(aD[1], Dx, gx0y[k]);
            fma2(aD[2], Dx, gx1x[k]); fma2(aD[3], Dx, gx1y[k]);
            fma2(aI[0], Rx, gx0x[k]); fma2(aI[1], Rx, gx0y[k]);
            fma2(aI[2], Rx, gx1x[k]); fma2(aI[3], Rx, gx1y[k]);
        }
    }

    // ---- per-warp -> shared ----
    v1m[w][lane] = s1m;
    {
        const int basej = i * 16 + jh * 8;
#pragma unroll
        for (int k = 0; k < 4; k++) {
            pti[w][basej + 2 * k] = lo32(aD[k]);
            pti[w][basej + 2 * k + 1] = hi32(aD[k]);
            pti[w][256 + basej + 2 * k] = lo32(aI[k]);
            pti[w][256 + basej + 2 * k + 1] = hi32(aI[k]);
        }
    }
    __syncthreads();

    // ---- block reduce -> deterministic per-block partial slot ----
    Part* gp = &g_part[b * GX + bx];
#pragma unroll
    for (int e0 = 0; e0 < 512; e0 += 256) {
        int e = e0 + t;
        float sum = 0.0f;
#pragma unroll
        for (int ww = 0; ww < NWPB; ww++) sum += pti[ww][e];
        gp->e[e] = sum;
    }
    if (t < 16) {
        float sum = 0.0f;
#pragma unroll
        for (int ww = 0; ww < NWPB; ww++) sum += v1m[ww][t] + v1m[ww][t + 16];
        gp->e[512 + t] = -sum;   // S1M = -sum(v*log2(1-m))
    }

    __threadfence();
    __syncthreads();
    if (t == 0) {
        int old = atomicAdd(&g_count, 1);
        is_last = (old == NBLK - 1);
    }
    __syncthreads();
    if (!is_last) return;

    if (t == 0) g_count = 0;

    // ---- final reduce: 9 entries per thread, jammed for MLP ----
    {
        float sacc[9];
        const float* bas[9];
        int ok[9];
#pragma unroll
        for (int k = 0; k < 9; k++) {
            int q = t + k * 256;
            ok[k] = (q < NE_TOT);
            sacc[k] = 0.0f;
            if (ok[k]) {
                int bb2 = q / NE_REAL;
                int e = q - bb2 * NE_REAL;
                bas[k] = &g_part[bb2 * GX].e[e];
            } else {
                bas[k] = &g_part[0].e[0];
            }
        }
        for (int gx = 0; gx < GX; gx++) {
#pragma unroll
            for (int k = 0; k < 9; k++)
                if (ok[k]) sacc[k] += bas[k][(size_t)gx * ENT];
        }
#pragma unroll
        for (int k = 0; k < 9; k++) {
            int q = t + k * 256;
            if (ok[k]) facc[q] = sacc[k];
        }
    }
    __syncthreads();

    // ---- marginals from INTER (+ direct S1M) ----
    if (t < BB * KK) {
        int bb2 = t / KK, q = t % KK;
        const float* F = facc + bb2 * NE_REAL;
        float summ = 0.0f, sumg = 0.0f;
#pragma unroll
        for (int x = 0; x < KK; x++) {
            summ += F[256 + q * 16 + x];   // row sum of INTER
            sumg += F[256 + x * 16 + q];   // col sum of INTER
        }
        mS1M[bb2][q] = F[512 + q];
        mSUMM[bb2][q] = summ;
        mSUMG[bb2][q] = sumg;
    }
    __syncthreads();
    if (t < BB) {
        float v = 0.0f;
#pragma unroll
        for (int x = 0; x < KK; x++) v += mSUMG[t][x];
        mV[t] = v;
    }
    __syncthreads();

    // ---- cost matrices ----
    const float LN2 = 0.69314718055994530942f;
    for (int idx = t; idx < BB * 256; idx += 256) {
        int bb2 = idx >> 8;
        int r = idx & 255;
        int ii = r >> 4, jj = r & 15;
        const float* F = facc + bb2 * NE_REAL;
        float denom = fmaxf(mV[bb2], 1.0f);
        float ce = LN2 * (F[ii * 16 + jj] + mS1M[bb2][ii]) / denom;
        float dice = 1.0f - 2.0f * F[256 + ii * 16 + jj] /
                                (mSUMM[bb2][ii] + mSUMG[bb2][jj] + EPSF);
        cost[bb2][ii][jj] = W_CE * ce + W_DICE * dice;
    }
    __syncthreads();

    // ---- warp-parallel Hungarian (JV), one warp per batch ----
    if (w < BB) {
        const int bb2 = w;
        float ur = 0.0f;
        float vv = 0.0f;
        int pcol = 0;

        for (int ii = 1; ii <= KK; ii++) {
            if (lane == 0) pcol = ii;
            float minv = 1e30f;
            int way = 0;
            int used = 0;
            int rowcov = 0;
            int j0 = 0;

            while (true) {
                if (lane == j0) used = 1;
                int i0 = __shfl_sync(FULL, pcol, j0);
                if (lane == i0) rowcov = 1;
                float u_i0 = __shfl_sync(FULL, ur, i0);

                int active = (lane >= 1 && lane <= KK && !used);
                if (active) {
                    float c = cost[bb2][i0 - 1][lane - 1];
                    float cur = c - u_i0 - vv;
                    if (cur < minv) { minv = cur; way = j0; }
                }
                float val = active ? minv : 1e30f;
                float red = val;
#pragma unroll
                for (int off = 16; off; off >>= 1)
                    red = fminf(red, __shfl_xor_sync(FULL, red, off));
                unsigned bal = __ballot_sync(FULL, val == red);
                int j1 = __ffs(bal) - 1;
                float delta = red;

                if (rowcov) ur += delta;
                if (used) vv -= delta;
                else if (lane >= 1 && lane <= KK) minv -= delta;

                j0 = j1;
                int pj = __shfl_sync(FULL, pcol, j0);
                if (pj == 0) break;
            }
            while (j0 != 0) {
                int j1 = __shfl_sync(FULL, way, j0);
                int pv = __shfl_sync(FULL, pcol, j1);
                if (lane == j0) pcol = pv;
                j0 = j1;
            }
        }
        if (lane >= 1 && lane <= KK) colmap[bb2][pcol - 1] = lane - 1;
    }
    __syncthreads();

    // ---- loss ----
    if (t < BB * KK) {
        int bb2 = t / KK, ii = t % KK;
        int jj = colmap[bb2][ii];
        const float* F = facc + bb2 * NE_REAL;
        rce[t] = LN2 * (F[ii * 16 + jj] + mS1M[bb2][ii]);
        rdice[t] = 1.0f - 2.0f * F[256 + ii * 16 + jj] /
                              (mSUMM[bb2][ii] + mSUMG[bb2][jj] + EPSF);
    }
    __syncthreads();

    if (t == 0) {
        float cs = 0.0f, ds = 0.0f, vt = 0.0f;
        for (int x = 0; x < BB * KK; x++) { cs += rce[x]; ds += rdice[x]; }
        for (int bb2 = 0; bb2 < BB; bb2++) vt += mV[bb2];
        float l_ce = cs / (fmaxf(vt, 1.0f) * (float)KK);
        float l_dice = ds / (float)(BB * KK);
        out[0] = W_CE * l_ce + W_DICE * l_dice;
    }
}

// ---------------------------------------------------------------------------
extern "C" void kernel_launch(void* const* d_in, const int* in_sizes, int n_in,
                              void* d_out, int out_size) {
    const float* mask = (const float*)d_in[0];
    const float* gt = (const float*)d_in[1];
    const float* valid = (const float*)d_in[2];
    float* out = (float*)d_out;

    dim3 grid(GX, BB);
    fused_kernel<<<grid, 256>>>(mask, gt, valid, out);
}